// round 2
// baseline (speedup 1.0000x reference)
#include <cuda_runtime.h>
#include <math.h>

#define Bn   4
#define Sn   2048
#define HIDn 1024
#define NHn  16
#define Dn   64
#define BHn  (Bn*NHn)     // 64
#define Mn   (Bn*Sn)      // 8192

// Scratch (static device globals — no runtime allocation allowed)
__device__ float g_q[(size_t)BHn*Sn*Dn];   // 33.5 MB, layout [bh][s][d]
__device__ float g_k[(size_t)BHn*Sn*Dn];
__device__ float g_v[(size_t)BHn*Sn*Dn];
__device__ float g_m[(size_t)BHn*Sn];      // row max
__device__ float g_l[(size_t)BHn*Sn];      // row sumexp

// ---------------------------------------------------------------------------
// K1: fused QKV projection.  y = x @ W^T + b, written as [bh][s][d].
// 128x128 tile, BK=16, double-buffered smem, 256 threads, 8x8 per thread.
// ---------------------------------------------------------------------------
__global__ __launch_bounds__(256) void qkv_kernel(
    const float* __restrict__ x,
    const float* __restrict__ Wq, const float* __restrict__ bq,
    const float* __restrict__ Wk, const float* __restrict__ bk,
    const float* __restrict__ Wv, const float* __restrict__ bv)
{
    __shared__ float As[2][16][128];
    __shared__ float Bs[2][16][128];

    const int t  = threadIdx.x;
    const int tx = t & 15;
    const int ty = t >> 4;
    const int which = blockIdx.z;
    const float* W    = (which == 0) ? Wq : ((which == 1) ? Wk : Wv);
    const float* bias = (which == 0) ? bq : ((which == 1) ? bk : bv);
    float* out        = (which == 0) ? g_q : ((which == 1) ? g_k : g_v);

    const int m0 = blockIdx.x * 128;
    const int n0 = blockIdx.y * 128;

    // Loader mapping: two float4 per matrix per tile
    const int rowA = t >> 2;          // 0..63
    const int rowB = rowA + 64;       // 64..127
    const int kq   = (t & 3) * 4;     // 0,4,8,12

    const float* xg0 = x + (size_t)(m0 + rowA) * HIDn + kq;
    const float* xg1 = x + (size_t)(m0 + rowB) * HIDn + kq;
    const float* wg0 = W + (size_t)(n0 + rowA) * HIDn + kq;
    const float* wg1 = W + (size_t)(n0 + rowB) * HIDn + kq;

    float acc[8][8];
#pragma unroll
    for (int i = 0; i < 8; i++)
#pragma unroll
        for (int j = 0; j < 8; j++) acc[i][j] = 0.0f;

    // prefetch tile 0
    float4 ra0 = *(const float4*)(xg0);
    float4 ra1 = *(const float4*)(xg1);
    float4 rb0 = *(const float4*)(wg0);
    float4 rb1 = *(const float4*)(wg1);

    As[0][kq+0][rowA] = ra0.x; As[0][kq+1][rowA] = ra0.y; As[0][kq+2][rowA] = ra0.z; As[0][kq+3][rowA] = ra0.w;
    As[0][kq+0][rowB] = ra1.x; As[0][kq+1][rowB] = ra1.y; As[0][kq+2][rowB] = ra1.z; As[0][kq+3][rowB] = ra1.w;
    Bs[0][kq+0][rowA] = rb0.x; Bs[0][kq+1][rowA] = rb0.y; Bs[0][kq+2][rowA] = rb0.z; Bs[0][kq+3][rowA] = rb0.w;
    Bs[0][kq+0][rowB] = rb1.x; Bs[0][kq+1][rowB] = rb1.y; Bs[0][kq+2][rowB] = rb1.z; Bs[0][kq+3][rowB] = rb1.w;
    __syncthreads();

    const int NK = HIDn / 16;   // 64 k-tiles
    for (int kt = 0; kt < NK; kt++) {
        const int cur = kt & 1;
        if (kt + 1 < NK) {
            const int off = (kt + 1) * 16;
            ra0 = *(const float4*)(xg0 + off);
            ra1 = *(const float4*)(xg1 + off);
            rb0 = *(const float4*)(wg0 + off);
            rb1 = *(const float4*)(wg1 + off);
        }
#pragma unroll 8
        for (int k = 0; k < 16; k++) {
            float a[8];
#pragma unroll
            for (int i = 0; i < 8; i++) a[i] = As[cur][k][ty + 16*i];
            float4 b0 = *(const float4*)&Bs[cur][k][tx*4];
            float4 b1 = *(const float4*)&Bs[cur][k][64 + tx*4];
#pragma unroll
            for (int i = 0; i < 8; i++) {
                acc[i][0] += a[i]*b0.x; acc[i][1] += a[i]*b0.y;
                acc[i][2] += a[i]*b0.z; acc[i][3] += a[i]*b0.w;
                acc[i][4] += a[i]*b1.x; acc[i][5] += a[i]*b1.y;
                acc[i][6] += a[i]*b1.z; acc[i][7] += a[i]*b1.w;
            }
        }
        if (kt + 1 < NK) {
            const int nxt = (kt + 1) & 1;
            As[nxt][kq+0][rowA] = ra0.x; As[nxt][kq+1][rowA] = ra0.y; As[nxt][kq+2][rowA] = ra0.z; As[nxt][kq+3][rowA] = ra0.w;
            As[nxt][kq+0][rowB] = ra1.x; As[nxt][kq+1][rowB] = ra1.y; As[nxt][kq+2][rowB] = ra1.z; As[nxt][kq+3][rowB] = ra1.w;
            Bs[nxt][kq+0][rowA] = rb0.x; Bs[nxt][kq+1][rowA] = rb0.y; Bs[nxt][kq+2][rowA] = rb0.z; Bs[nxt][kq+3][rowA] = rb0.w;
            Bs[nxt][kq+0][rowB] = rb1.x; Bs[nxt][kq+1][rowB] = rb1.y; Bs[nxt][kq+2][rowB] = rb1.z; Bs[nxt][kq+3][rowB] = rb1.w;
            __syncthreads();
        }
    }

    // epilogue: add bias, scatter to [bh][s][d]
#pragma unroll
    for (int i = 0; i < 8; i++) {
        const int m = m0 + ty + 16*i;
        const int bidx = m >> 11;          // /2048
        const int s    = m & (Sn - 1);
#pragma unroll
        for (int jj = 0; jj < 2; jj++) {
            const int n = n0 + jj*64 + tx*4;
            const int h = n >> 6;
            const int d = n & 63;
            float4 bi = *(const float4*)&bias[n];
            float4 o;
            o.x = acc[i][jj*4+0] + bi.x;
            o.y = acc[i][jj*4+1] + bi.y;
            o.z = acc[i][jj*4+2] + bi.z;
            o.w = acc[i][jj*4+3] + bi.w;
            *(float4*)&out[((size_t)(bidx*NHn + h) * Sn + s) * Dn + d] = o;
        }
    }
}

// ---------------------------------------------------------------------------
// K2: scores = Q K^T / 8 + mask, written raw into probs buffer (scratch),
// with online row-max / row-sumexp tracked in registers (16-lane shfl).
// Grid: (S/128 q-tiles, BH). 128x128 score tile per CTA, K-dim = 64.
// ---------------------------------------------------------------------------
__global__ __launch_bounds__(256) void scores_kernel(
    const float* __restrict__ mask, float* __restrict__ probs)
{
    extern __shared__ float sm2[];
    float* Qs  = sm2;              // [128][65]
    float* Kst = sm2 + 128*65;     // [64][128] transposed key tile

    const int t  = threadIdx.x;
    const int tx = t & 15;
    const int ty = t >> 4;
    const int qt = blockIdx.x;
    const int bh = blockIdx.y;
    const int bidx = bh >> 4;

    // load Q tile [128 rows][64 d]
    const float* qbase = g_q + (size_t)bh * Sn * Dn + (size_t)qt * 128 * Dn;
#pragma unroll
    for (int i = 0; i < 8; i++) {
        const int f = t + 256*i;
        const int r = f >> 4;
        const int d4 = (f & 15) * 4;
        float4 v = *(const float4*)(qbase + r*Dn + d4);
        Qs[r*65 + d4 + 0] = v.x; Qs[r*65 + d4 + 1] = v.y;
        Qs[r*65 + d4 + 2] = v.z; Qs[r*65 + d4 + 3] = v.w;
    }

    float mi[8], li[8];
#pragma unroll
    for (int i = 0; i < 8; i++) { mi[i] = -1e30f; li[i] = 0.0f; }

    for (int kt = 0; kt < Sn/128; kt++) {
        __syncthreads();
        // load K tile transposed: Kst[d][c]
        const float* kb = g_k + (size_t)bh * Sn * Dn + (size_t)kt * 128 * Dn;
#pragma unroll
        for (int i = 0; i < 8; i++) {
            const int f = t + 256*i;
            const int c = f >> 4;
            const int d4 = (f & 15) * 4;
            float4 v = *(const float4*)(kb + c*Dn + d4);
            Kst[(d4+0)*128 + c] = v.x; Kst[(d4+1)*128 + c] = v.y;
            Kst[(d4+2)*128 + c] = v.z; Kst[(d4+3)*128 + c] = v.w;
        }
        __syncthreads();

        float acc[8][8];
#pragma unroll
        for (int i = 0; i < 8; i++)
#pragma unroll
            for (int j = 0; j < 8; j++) acc[i][j] = 0.0f;

#pragma unroll 8
        for (int d = 0; d < 64; d++) {
            float a[8];
#pragma unroll
            for (int i = 0; i < 8; i++) a[i] = Qs[(ty + 16*i)*65 + d];
            float4 b0 = *(const float4*)&Kst[d*128 + tx*4];
            float4 b1 = *(const float4*)&Kst[d*128 + 64 + tx*4];
#pragma unroll
            for (int i = 0; i < 8; i++) {
                acc[i][0] += a[i]*b0.x; acc[i][1] += a[i]*b0.y;
                acc[i][2] += a[i]*b0.z; acc[i][3] += a[i]*b0.w;
                acc[i][4] += a[i]*b1.x; acc[i][5] += a[i]*b1.y;
                acc[i][6] += a[i]*b1.z; acc[i][7] += a[i]*b1.w;
            }
        }

        const float* mrow = mask + (size_t)bidx * Sn + kt*128;
        float4 mk0 = *(const float4*)&mrow[tx*4];
        float4 mk1 = *(const float4*)&mrow[64 + tx*4];

#pragma unroll
        for (int i = 0; i < 8; i++) {
            float sc[8];
            sc[0] = acc[i][0]*0.125f + mk0.x; sc[1] = acc[i][1]*0.125f + mk0.y;
            sc[2] = acc[i][2]*0.125f + mk0.z; sc[3] = acc[i][3]*0.125f + mk0.w;
            sc[4] = acc[i][4]*0.125f + mk1.x; sc[5] = acc[i][5]*0.125f + mk1.y;
            sc[6] = acc[i][6]*0.125f + mk1.z; sc[7] = acc[i][7]*0.125f + mk1.w;

            float tmax = sc[0];
#pragma unroll
            for (int j = 1; j < 8; j++) tmax = fmaxf(tmax, sc[j]);
#pragma unroll
            for (int o = 8; o >= 1; o >>= 1)
                tmax = fmaxf(tmax, __shfl_xor_sync(0xffffffffu, tmax, o, 16));
            const float mnew = fmaxf(mi[i], tmax);
            float ps = 0.0f;
#pragma unroll
            for (int j = 0; j < 8; j++) ps += __expf(sc[j] - mnew);
#pragma unroll
            for (int o = 8; o >= 1; o >>= 1)
                ps += __shfl_xor_sync(0xffffffffu, ps, o, 16);
            li[i] = li[i] * __expf(mi[i] - mnew) + ps;
            mi[i] = mnew;

            const size_t ro = ((size_t)bh * Sn + qt*128 + ty + 16*i) * Sn + kt*128;
            *(float4*)&probs[ro + tx*4]      = make_float4(sc[0], sc[1], sc[2], sc[3]);
            *(float4*)&probs[ro + 64 + tx*4] = make_float4(sc[4], sc[5], sc[6], sc[7]);
        }
    }

    if (tx == 0) {
#pragma unroll
        for (int i = 0; i < 8; i++) {
            const size_t ro = (size_t)bh * Sn + qt*128 + ty + 16*i;
            g_m[ro] = mi[i];
            g_l[ro] = li[i];
        }
    }
}

// ---------------------------------------------------------------------------
// K3: read raw scores, p = exp(s - m)/l → final probs (written back),
// and ctx = P @ V accumulated in the same pass.
// Grid: (S/128 q-tiles, BH). K-tile = 64 keys.
// ---------------------------------------------------------------------------
__global__ __launch_bounds__(256) void ctx_kernel(
    float* __restrict__ probs, float* __restrict__ ctx)
{
    extern __shared__ float sm3[];
    float* Ps = sm3;                    // [128][65]
    float* Vs = sm3 + 128*65;           // [64][64]
    float* ms = sm3 + 128*65 + 64*64;   // [128]
    float* lv = ms + 128;               // [128]

    const int t  = threadIdx.x;
    const int tx = t & 15;
    const int ty = t >> 4;
    const int qt = blockIdx.x;
    const int bh = blockIdx.y;
    const int bidx = bh >> 4;
    const int h    = bh & 15;
    const int q0 = qt * 128;

    if (t < 128) {
        const size_t ro = (size_t)bh * Sn + q0 + t;
        ms[t] = g_m[ro];
        lv[t] = 1.0f / g_l[ro];
    }

    float acc[8][4];
#pragma unroll
    for (int i = 0; i < 8; i++)
#pragma unroll
        for (int j = 0; j < 4; j++) acc[i][j] = 0.0f;

    for (int kt = 0; kt < Sn/64; kt++) {
        __syncthreads();
        // V tile [64 k][64 d] straight copy
        const float* vbase = g_v + (size_t)bh * Sn * Dn + (size_t)kt * 64 * Dn;
#pragma unroll
        for (int i = 0; i < 4; i++) {
            const int f = t + 256*i;
            float4 v = *(const float4*)(vbase + f*4);
            *(float4*)&Vs[f*4] = v;
        }
        // P tile: load raw scores, normalize, write back final probs, stage smem
#pragma unroll
        for (int i = 0; i < 8; i++) {
            const int f = t + 256*i;
            const int r = f >> 4;
            const int c4 = (f & 15) * 4;
            const size_t gi = ((size_t)bh * Sn + q0 + r) * Sn + kt*64 + c4;
            float4 s4 = *(const float4*)&probs[gi];
            const float mm = ms[r];
            const float ll = lv[r];
            s4.x = __expf(s4.x - mm) * ll;
            s4.y = __expf(s4.y - mm) * ll;
            s4.z = __expf(s4.z - mm) * ll;
            s4.w = __expf(s4.w - mm) * ll;
            *(float4*)&probs[gi] = s4;
            Ps[r*65 + c4 + 0] = s4.x; Ps[r*65 + c4 + 1] = s4.y;
            Ps[r*65 + c4 + 2] = s4.z; Ps[r*65 + c4 + 3] = s4.w;
        }
        __syncthreads();

#pragma unroll 16
        for (int k = 0; k < 64; k++) {
            float4 v = *(const float4*)&Vs[k*64 + tx*4];
#pragma unroll
            for (int i = 0; i < 8; i++) {
                const float a = Ps[(ty + 16*i)*65 + k];
                acc[i][0] += a * v.x;
                acc[i][1] += a * v.y;
                acc[i][2] += a * v.z;
                acc[i][3] += a * v.w;
            }
        }
    }

    // epilogue: ctx[b][s][h*64+d]
#pragma unroll
    for (int i = 0; i < 8; i++) {
        const int row = q0 + ty + 16*i;
        float4 o = make_float4(acc[i][0], acc[i][1], acc[i][2], acc[i][3]);
        *(float4*)&ctx[((size_t)(bidx * Sn + row)) * HIDn + h*64 + tx*4] = o;
    }
}

// ---------------------------------------------------------------------------
extern "C" void kernel_launch(void* const* d_in, const int* in_sizes, int n_in,
                              void* d_out, int out_size)
{
    const float* x    = (const float*)d_in[0];
    const float* mask = (const float*)d_in[1];
    const float* Wq   = (const float*)d_in[2];
    const float* bq   = (const float*)d_in[3];
    const float* Wk   = (const float*)d_in[4];
    const float* bk   = (const float*)d_in[5];
    const float* Wv   = (const float*)d_in[6];
    const float* bv   = (const float*)d_in[7];

    float* ctx = (float*)d_out;
    const size_t PROBS_ELEMS = (size_t)BHn * Sn * Sn;   // 268,435,456
    size_t probs_off = 0;
    if ((size_t)out_size > PROBS_ELEMS) probs_off = (size_t)out_size - PROBS_ELEMS;
    float* probs = (float*)d_out + probs_off;

    const int smem2 = (128*65 + 64*128) * (int)sizeof(float);           // 66,048 B
    const int smem3 = (128*65 + 64*64 + 128 + 128) * (int)sizeof(float); // 50,688 B
    cudaFuncSetAttribute(scores_kernel, cudaFuncAttributeMaxDynamicSharedMemorySize, smem2);
    cudaFuncSetAttribute(ctx_kernel,    cudaFuncAttributeMaxDynamicSharedMemorySize, smem3);

    qkv_kernel<<<dim3(Mn/128, HIDn/128, 3), 256>>>(x, Wq, bq, Wk, bk, Wv, bv);
    scores_kernel<<<dim3(Sn/128, BHn), 256, smem2>>>(mask, probs);
    ctx_kernel<<<dim3(Sn/128, BHn), 256, smem3>>>(probs, ctx);
}

// round 4
// speedup vs baseline: 1.8290x; 1.8290x over previous
#include <cuda_runtime.h>
#include <cuda_bf16.h>
#include <math.h>
#include <stdint.h>

#define Bn   4
#define Sn   2048
#define HIDn 1024
#define NHn  16
#define Dn   64
#define BHn  64
#define Mn   8192

// ---------------- scratch (static device globals; no runtime alloc) --------
__device__ __nv_bfloat16 g_xh[(size_t)Mn * HIDn];
__device__ __nv_bfloat16 g_xl[(size_t)Mn * HIDn];
__device__ __nv_bfloat16 g_wh[(size_t)3 * HIDn * HIDn];
__device__ __nv_bfloat16 g_wl[(size_t)3 * HIDn * HIDn];
__device__ __nv_bfloat16 g_qh[(size_t)BHn * Sn * Dn];
__device__ __nv_bfloat16 g_ql[(size_t)BHn * Sn * Dn];
__device__ __nv_bfloat16 g_kh[(size_t)BHn * Sn * Dn];
__device__ __nv_bfloat16 g_kl[(size_t)BHn * Sn * Dn];
__device__ float g_v[(size_t)BHn * Sn * Dn];
__device__ float g_m[(size_t)BHn * Sn];
__device__ float g_l[(size_t)BHn * Sn];

// ---------------- PTX helpers (baseline-feature PTX only: sm_80-era) -------
__device__ __forceinline__ uint32_t smem_u32(const void* p) {
    uint32_t a;
    asm("{ .reg .u64 t; cvta.to.shared.u64 t, %1; cvt.u32.u64 %0, t; }" : "=r"(a) : "l"(p));
    return a;
}
#define CP_ASYNC(dst, src) \
    asm volatile("cp.async.cg.shared.global [%0], [%1], 16;" :: "r"(dst), "l"(src))
#define CP_COMMIT() asm volatile("cp.async.commit_group;")
#define CP_WAIT0()  asm volatile("cp.async.wait_group 0;")
#define CP_WAIT1()  asm volatile("cp.async.wait_group 1;")

__device__ __forceinline__ void ldsm4(uint32_t r[4], uint32_t addr) {
    asm volatile("ldmatrix.sync.aligned.m8n8.x4.shared.b16 {%0,%1,%2,%3}, [%4];"
        : "=r"(r[0]), "=r"(r[1]), "=r"(r[2]), "=r"(r[3]) : "r"(addr));
}
__device__ __forceinline__ void mma16816(float c[4], const uint32_t a[4],
                                         uint32_t b0, uint32_t b1) {
    asm volatile("mma.sync.aligned.m16n8k16.row.col.f32.bf16.bf16.f32 "
        "{%0,%1,%2,%3}, {%4,%5,%6,%7}, {%8,%9}, {%0,%1,%2,%3};"
        : "+f"(c[0]), "+f"(c[1]), "+f"(c[2]), "+f"(c[3])
        : "r"(a[0]), "r"(a[1]), "r"(a[2]), "r"(a[3]), "r"(b0), "r"(b1));
}

// ---------------- fp32 -> (bf16 hi, bf16 lo) split --------------------------
__device__ __forceinline__ void split1(float v, uint16_t& h, uint16_t& l) {
    __nv_bfloat16 hb = __float2bfloat16(v);
    float r = v - __bfloat162float(hb);
    h = __bfloat16_as_ushort(hb);
    l = __bfloat16_as_ushort(__float2bfloat16(r));
}

__global__ __launch_bounds__(256) void split_x_kernel(const float4* __restrict__ src) {
    size_t i = (size_t)blockIdx.x * 256 + threadIdx.x;
    float4 v = src[i];
    uint16_t h0,h1,h2,h3,l0,l1,l2,l3;
    split1(v.x,h0,l0); split1(v.y,h1,l1); split1(v.z,h2,l2); split1(v.w,h3,l3);
    uint2 uh, ul;
    uh.x = ((uint32_t)h1<<16)|h0; uh.y = ((uint32_t)h3<<16)|h2;
    ul.x = ((uint32_t)l1<<16)|l0; ul.y = ((uint32_t)l3<<16)|l2;
    ((uint2*)g_xh)[i] = uh; ((uint2*)g_xl)[i] = ul;
}

__global__ __launch_bounds__(256) void split_w_kernel(const float4* __restrict__ Wq,
                                                      const float4* __restrict__ Wk,
                                                      const float4* __restrict__ Wv) {
    const int which = blockIdx.y;
    const float4* W = (which == 0) ? Wq : ((which == 1) ? Wk : Wv);
    size_t i = (size_t)blockIdx.x * 256 + threadIdx.x;
    float4 v = W[i];
    uint16_t h0,h1,h2,h3,l0,l1,l2,l3;
    split1(v.x,h0,l0); split1(v.y,h1,l1); split1(v.z,h2,l2); split1(v.w,h3,l3);
    uint2 uh, ul;
    uh.x = ((uint32_t)h1<<16)|h0; uh.y = ((uint32_t)h3<<16)|h2;
    ul.x = ((uint32_t)l1<<16)|l0; ul.y = ((uint32_t)l3<<16)|l2;
    size_t o = (size_t)which * (HIDn * HIDn / 4) + i;
    ((uint2*)g_wh)[o] = uh; ((uint2*)g_wl)[o] = ul;
}

// Tile: 128 rows x 64 bf16 (128B data + 16B pad = 144B row stride).
// 144r mod 128 cycles all 8 16B-groups -> ldmatrix conflict-free.
#define ROWB 144
#define T1   (128 * ROWB)     // 18432 B per tile

// ---------------------------------------------------------------------------
// K1: QKV projection, y = x @ W^T + b.  CTA = 128x128 tile, K=1024 in 16
// chunks of 64.  3x bf16-split mma.sync, cp.async double-buffered.
// ---------------------------------------------------------------------------
#define K1_SMEM (8 * T1)      // 147456 B

__global__ __launch_bounds__(256) void qkv_mma(
    const float* __restrict__ bq, const float* __restrict__ bk, const float* __restrict__ bv)
{
    extern __shared__ char smem[];
    const uint32_t sb = smem_u32(smem);
    const int tid = threadIdx.x;
    const int lane = tid & 31;
    const int wid = tid >> 5;
    const int warp_m = wid & 1;        // 2 x 64 rows
    const int warp_n = wid >> 1;       // 4 x 32 cols
    const int which = blockIdx.z;
    const int m0 = blockIdx.x * 128;
    const int n0 = blockIdx.y * 128;
    const float* bias = (which == 0) ? bq : ((which == 1) ? bk : bv);
    const __nv_bfloat16* wh = g_wh + (size_t)which * HIDn * HIDn;
    const __nv_bfloat16* wl = g_wl + (size_t)which * HIDn * HIDn;

    float C[4][4][4];
#pragma unroll
    for (int a = 0; a < 4; a++)
#pragma unroll
        for (int n = 0; n < 4; n++)
#pragma unroll
            for (int j = 0; j < 4; j++) C[a][n][j] = 0.0f;

    // -------- loader --------
    auto load_chunk = [&](int chunk, int buf) {
        const int kc = chunk * 64;
        const uint32_t bufb = sb + buf * 4 * T1;
#pragma unroll
        for (int t = 0; t < 4; t++) {
            const __nv_bfloat16* src = (t == 0) ? g_xh : (t == 1) ? g_xl : (t == 2) ? wh : wl;
            const int rbase = (t < 2) ? m0 : n0;
#pragma unroll
            for (int i = 0; i < 4; i++) {
                const int idx = tid + 256 * i;          // 0..1023
                const int row = idx >> 3, c = idx & 7;
                CP_ASYNC(bufb + t * T1 + row * ROWB + c * 16,
                         src + (size_t)(rbase + row) * HIDn + kc + c * 8);
            }
        }
        CP_COMMIT();
    };

    // -------- compute --------
    auto compute = [&](int buf) {
        const uint32_t base = sb + buf * 4 * T1;
#pragma unroll
        for (int ks = 0; ks < 4; ks++) {
            uint32_t ah[4][4], al[4][4];
#pragma unroll
            for (int a = 0; a < 4; a++) {
                const int row = warp_m * 64 + a * 16 + ((lane >> 3) & 1) * 8 + (lane & 7);
                const int colb = ks * 32 + (lane >> 4) * 16;
                ldsm4(ah[a], base + row * ROWB + colb);
                ldsm4(al[a], base + T1 + row * ROWB + colb);
            }
            uint32_t bh[2][4], bl[2][4];
#pragma unroll
            for (int p = 0; p < 2; p++) {
                const int row = warp_n * 32 + p * 16 + ((lane >> 4) & 1) * 8 + (lane & 7);
                const int colb = ks * 32 + ((lane >> 3) & 1) * 16;
                ldsm4(bh[p], base + 2 * T1 + row * ROWB + colb);
                ldsm4(bl[p], base + 3 * T1 + row * ROWB + colb);
            }
#pragma unroll
            for (int a = 0; a < 4; a++)
#pragma unroll
                for (int n = 0; n < 4; n++) {
                    const int p = n >> 1, q = (n & 1) * 2;
                    mma16816(C[a][n], ah[a], bh[p][q], bh[p][q + 1]);
                    mma16816(C[a][n], ah[a], bl[p][q], bl[p][q + 1]);
                    mma16816(C[a][n], al[a], bh[p][q], bh[p][q + 1]);
                }
        }
    };

    load_chunk(0, 0);
    load_chunk(1, 1);
    for (int kt = 0; kt < 16; kt++) {
        if (kt == 15) { CP_WAIT0(); } else { CP_WAIT1(); }
        __syncthreads();
        compute(kt & 1);
        __syncthreads();
        if (kt + 2 < 16) load_chunk(kt + 2, kt & 1);
    }

    // -------- epilogue: bias + split + scatter to [bh][s][d] ----------------
    __nv_bfloat16* oh = (which == 0) ? g_qh : g_kh;
    __nv_bfloat16* ol = (which == 0) ? g_ql : g_kl;
#pragma unroll
    for (int a = 0; a < 4; a++)
#pragma unroll
        for (int n = 0; n < 4; n++) {
            const int row0 = m0 + warp_m * 64 + a * 16 + (lane >> 2);
            const int col  = n0 + warp_n * 32 + n * 8 + (lane & 3) * 2;
            const float bb0 = bias[col], bb1 = bias[col + 1];
            const int hd = col >> 6, d = col & 63;
#pragma unroll
            for (int h = 0; h < 2; h++) {
                const int row = row0 + h * 8;
                const float v0 = C[a][n][h * 2 + 0] + bb0;
                const float v1 = C[a][n][h * 2 + 1] + bb1;
                const int bidx = row >> 11, s = row & (Sn - 1);
                const size_t oi = ((size_t)(bidx * NHn + hd) * Sn + s) * Dn + d;
                if (which == 2) {
                    *(float2*)&g_v[oi] = make_float2(v0, v1);
                } else {
                    uint16_t h0, h1, l0, l1;
                    split1(v0, h0, l0); split1(v1, h1, l1);
                    *(uint32_t*)&oh[oi] = ((uint32_t)h1 << 16) | h0;
                    *(uint32_t*)&ol[oi] = ((uint32_t)l1 << 16) | l0;
                }
            }
        }
}

// ---------------------------------------------------------------------------
// K2: scores = QK^T/8 + mask -> raw into probs, with online per-row (m,l).
// CTA = 128 q x 128 k tile, d=64, 3x bf16-split mma.sync.
// smem: QH|QL (static), KH/KL double-buffered, mask, reduction arrays.
// ---------------------------------------------------------------------------
#define K2_MASKOFF (6 * T1)                    // 110592
#define K2_REDM    (K2_MASKOFF + Sn * 4)       // 118784
#define K2_REDL    (K2_REDM + 4 * 128 * 4)     // 120832
#define K2_SMEM    (K2_REDL + 4 * 128 * 4)     // 122880

__global__ __launch_bounds__(256) void scores_mma(
    const float* __restrict__ mask, float* __restrict__ probs)
{
    extern __shared__ char smem[];
    const uint32_t sb = smem_u32(smem);
    float* maskS = (float*)(smem + K2_MASKOFF);
    float* redM  = (float*)(smem + K2_REDM);
    float* redL  = (float*)(smem + K2_REDL);
    const int tid = threadIdx.x;
    const int lane = tid & 31;
    const int wid = tid >> 5;
    const int warp_m = wid & 1;
    const int warp_n = wid >> 1;
    const int qt = blockIdx.x;
    const int bh = blockIdx.y;
    const int bidx = bh >> 4;
    const int grow = qt * 128;

    // Q tiles (group 0, together with K tile 0)
    const size_t qgb = ((size_t)bh * Sn + grow) * Dn;
#pragma unroll
    for (int i = 0; i < 4; i++) {
        const int idx = tid + 256 * i;
        const int row = idx >> 3, c = idx & 7;
        CP_ASYNC(sb + row * ROWB + c * 16,      g_qh + qgb + row * Dn + c * 8);
        CP_ASYNC(sb + T1 + row * ROWB + c * 16, g_ql + qgb + row * Dn + c * 8);
    }
    // mask row (plain loads; visible after first __syncthreads)
#pragma unroll
    for (int i = 0; i < 2; i++)
        ((float4*)maskS)[tid + 256 * i] = ((const float4*)(mask + (size_t)bidx * Sn))[tid + 256 * i];

    auto load_k = [&](int kt, int buf) {
        const size_t kgb = ((size_t)bh * Sn + kt * 128) * Dn;
        const uint32_t bufb = sb + (2 + buf * 2) * T1;
#pragma unroll
        for (int i = 0; i < 4; i++) {
            const int idx = tid + 256 * i;
            const int row = idx >> 3, c = idx & 7;
            CP_ASYNC(bufb + row * ROWB + c * 16,      g_kh + kgb + row * Dn + c * 8);
            CP_ASYNC(bufb + T1 + row * ROWB + c * 16, g_kl + kgb + row * Dn + c * 8);
        }
        CP_COMMIT();
    };

    load_k(0, 0);          // group 0 includes Q + K0
    load_k(1, 1);          // group 1

    float sm_[8], sl_[8];
#pragma unroll
    for (int i = 0; i < 8; i++) { sm_[i] = -1e30f; sl_[i] = 0.0f; }

    for (int kt = 0; kt < 16; kt++) {
        if (kt == 15) { CP_WAIT0(); } else { CP_WAIT1(); }
        __syncthreads();

        const uint32_t kbase = sb + (2 + (kt & 1) * 2) * T1;
        float C[4][4][4];
#pragma unroll
        for (int a = 0; a < 4; a++)
#pragma unroll
            for (int n = 0; n < 4; n++)
#pragma unroll
                for (int j = 0; j < 4; j++) C[a][n][j] = 0.0f;

#pragma unroll
        for (int ks = 0; ks < 4; ks++) {
            uint32_t ah[4][4], al[4][4];
#pragma unroll
            for (int a = 0; a < 4; a++) {
                const int row = warp_m * 64 + a * 16 + ((lane >> 3) & 1) * 8 + (lane & 7);
                const int colb = ks * 32 + (lane >> 4) * 16;
                ldsm4(ah[a], sb + row * ROWB + colb);
                ldsm4(al[a], sb + T1 + row * ROWB + colb);
            }
            uint32_t bhf[2][4], blf[2][4];
#pragma unroll
            for (int p = 0; p < 2; p++) {
                const int row = warp_n * 32 + p * 16 + ((lane >> 4) & 1) * 8 + (lane & 7);
                const int colb = ks * 32 + ((lane >> 3) & 1) * 16;
                ldsm4(bhf[p], kbase + row * ROWB + colb);
                ldsm4(blf[p], kbase + T1 + row * ROWB + colb);
            }
#pragma unroll
            for (int a = 0; a < 4; a++)
#pragma unroll
                for (int n = 0; n < 4; n++) {
                    const int p = n >> 1, q = (n & 1) * 2;
                    mma16816(C[a][n], ah[a], bhf[p][q], bhf[p][q + 1]);
                    mma16816(C[a][n], ah[a], blf[p][q], blf[p][q + 1]);
                    mma16816(C[a][n], al[a], bhf[p][q], bhf[p][q + 1]);
                }
        }

        // epilogue: scale + mask, write raw scores, online stats
#pragma unroll
        for (int a = 0; a < 4; a++) {
            float s[4][4];
#pragma unroll
            for (int n = 0; n < 4; n++) {
                const int colt = warp_n * 32 + n * 8 + (lane & 3) * 2;
                const float mk0 = maskS[kt * 128 + colt];
                const float mk1 = maskS[kt * 128 + colt + 1];
                s[n][0] = C[a][n][0] * 0.125f + mk0;
                s[n][1] = C[a][n][1] * 0.125f + mk1;
                s[n][2] = C[a][n][2] * 0.125f + mk0;
                s[n][3] = C[a][n][3] * 0.125f + mk1;
                const int rt0 = warp_m * 64 + a * 16 + (lane >> 2);
                const size_t r0 = ((size_t)bh * Sn + grow + rt0) * Sn + kt * 128 + colt;
                const size_t r1 = ((size_t)bh * Sn + grow + rt0 + 8) * Sn + kt * 128 + colt;
                *(float2*)&probs[r0] = make_float2(s[n][0], s[n][1]);
                *(float2*)&probs[r1] = make_float2(s[n][2], s[n][3]);
            }
#pragma unroll
            for (int hh = 0; hh < 2; hh++) {
                float cm = s[0][hh * 2];
#pragma unroll
                for (int n = 0; n < 4; n++) {
                    cm = fmaxf(cm, s[n][hh * 2]);
                    cm = fmaxf(cm, s[n][hh * 2 + 1]);
                }
                const int si = a * 2 + hh;
                const float mn = fmaxf(sm_[si], cm);
                float ps = 0.0f;
#pragma unroll
                for (int n = 0; n < 4; n++)
                    ps += __expf(s[n][hh * 2] - mn) + __expf(s[n][hh * 2 + 1] - mn);
                sl_[si] = sl_[si] * __expf(sm_[si] - mn) + ps;
                sm_[si] = mn;
            }
        }

        __syncthreads();
        if (kt + 2 < 16) load_k(kt + 2, kt & 1);
    }

    // cross-lane (quad) then cross-warp_n reduction of (m,l)
#pragma unroll
    for (int i = 0; i < 8; i++) {
        float m = sm_[i], l = sl_[i];
#pragma unroll
        for (int off = 1; off <= 2; off <<= 1) {
            const float om = __shfl_xor_sync(0xffffffffu, m, off);
            const float ol = __shfl_xor_sync(0xffffffffu, l, off);
            const float mn = fmaxf(m, om);
            l = l * __expf(m - mn) + ol * __expf(om - mn);
            m = mn;
        }
        if ((lane & 3) == 0) {
            const int row = warp_m * 64 + (i >> 1) * 16 + (i & 1) * 8 + (lane >> 2);
            redM[warp_n * 128 + row] = m;
            redL[warp_n * 128 + row] = l;
        }
    }
    __syncthreads();
    if (tid < 128) {
        float m = redM[tid], l = redL[tid];
#pragma unroll
        for (int w = 1; w < 4; w++) {
            const float om = redM[w * 128 + tid];
            const float ol = redL[w * 128 + tid];
            const float mn = fmaxf(m, om);
            l = l * __expf(m - mn) + ol * __expf(om - mn);
            m = mn;
        }
        g_m[(size_t)bh * Sn + grow + tid] = m;
        g_l[(size_t)bh * Sn + grow + tid] = l;
    }
}

// ---------------------------------------------------------------------------
// K3 (proven SIMT): normalize probs in place and ctx = P @ V.
// ---------------------------------------------------------------------------
__global__ __launch_bounds__(256) void ctx_kernel(
    float* __restrict__ probs, float* __restrict__ ctx)
{
    extern __shared__ float sm3[];
    float* Ps = sm3;
    float* Vs = sm3 + 128*65;
    float* ms = sm3 + 128*65 + 64*64;
    float* lv = ms + 128;

    const int t  = threadIdx.x;
    const int tx = t & 15;
    const int ty = t >> 4;
    const int qt = blockIdx.x;
    const int bh = blockIdx.y;
    const int bidx = bh >> 4;
    const int h    = bh & 15;
    const int q0 = qt * 128;

    if (t < 128) {
        const size_t ro = (size_t)bh * Sn + q0 + t;
        ms[t] = g_m[ro];
        lv[t] = 1.0f / g_l[ro];
    }

    float acc[8][4];
#pragma unroll
    for (int i = 0; i < 8; i++)
#pragma unroll
        for (int j = 0; j < 4; j++) acc[i][j] = 0.0f;

    for (int kt = 0; kt < Sn/64; kt++) {
        __syncthreads();
        const float* vbase = g_v + (size_t)bh * Sn * Dn + (size_t)kt * 64 * Dn;
#pragma unroll
        for (int i = 0; i < 4; i++) {
            const int f = t + 256*i;
            float4 v = *(const float4*)(vbase + f*4);
            *(float4*)&Vs[f*4] = v;
        }
#pragma unroll
        for (int i = 0; i < 8; i++) {
            const int f = t + 256*i;
            const int r = f >> 4;
            const int c4 = (f & 15) * 4;
            const size_t gi = ((size_t)bh * Sn + q0 + r) * Sn + kt*64 + c4;
            float4 s4 = *(const float4*)&probs[gi];
            const float mm = ms[r];
            const float ll = lv[r];
            s4.x = __expf(s4.x - mm) * ll;
            s4.y = __expf(s4.y - mm) * ll;
            s4.z = __expf(s4.z - mm) * ll;
            s4.w = __expf(s4.w - mm) * ll;
            *(float4*)&probs[gi] = s4;
            Ps[r*65 + c4 + 0] = s4.x; Ps[r*65 + c4 + 1] = s4.y;
            Ps[r*65 + c4 + 2] = s4.z; Ps[r*65 + c4 + 3] = s4.w;
        }
        __syncthreads();

#pragma unroll 16
        for (int k = 0; k < 64; k++) {
            float4 v = *(const float4*)&Vs[k*64 + tx*4];
#pragma unroll
            for (int i = 0; i < 8; i++) {
                const float a = Ps[(ty + 16*i)*65 + k];
                acc[i][0] += a * v.x;
                acc[i][1] += a * v.y;
                acc[i][2] += a * v.z;
                acc[i][3] += a * v.w;
            }
        }
    }

#pragma unroll
    for (int i = 0; i < 8; i++) {
        const int row = q0 + ty + 16*i;
        float4 o = make_float4(acc[i][0], acc[i][1], acc[i][2], acc[i][3]);
        *(float4*)&ctx[((size_t)(bidx * Sn + row)) * HIDn + h*64 + tx*4] = o;
    }
}

// ---------------------------------------------------------------------------
extern "C" void kernel_launch(void* const* d_in, const int* in_sizes, int n_in,
                              void* d_out, int out_size)
{
    const float* x    = (const float*)d_in[0];
    const float* mask = (const float*)d_in[1];
    const float* Wq   = (const float*)d_in[2];
    const float* bq   = (const float*)d_in[3];
    const float* Wk   = (const float*)d_in[4];
    const float* bk   = (const float*)d_in[5];
    const float* Wv   = (const float*)d_in[6];
    const float* bv   = (const float*)d_in[7];

    float* ctx = (float*)d_out;
    const size_t PROBS_ELEMS = (size_t)BHn * Sn * Sn;
    size_t probs_off = 0;
    if ((size_t)out_size > PROBS_ELEMS) probs_off = (size_t)out_size - PROBS_ELEMS;
    float* probs = (float*)d_out + probs_off;

    const int smem3 = (128*65 + 64*64 + 128 + 128) * (int)sizeof(float);
    cudaFuncSetAttribute(qkv_mma,    cudaFuncAttributeMaxDynamicSharedMemorySize, K1_SMEM);
    cudaFuncSetAttribute(scores_mma, cudaFuncAttributeMaxDynamicSharedMemorySize, K2_SMEM);
    cudaFuncSetAttribute(ctx_kernel, cudaFuncAttributeMaxDynamicSharedMemorySize, smem3);

    split_x_kernel<<<Mn * HIDn / 4 / 256, 256>>>((const float4*)x);
    split_w_kernel<<<dim3(HIDn * HIDn / 4 / 256, 3), 256>>>(
        (const float4*)Wq, (const float4*)Wk, (const float4*)Wv);
    qkv_mma<<<dim3(Mn/128, HIDn/128, 3), 256, K1_SMEM>>>(bq, bk, bv);
    scores_mma<<<dim3(Sn/128, BHn), 256, K2_SMEM>>>(mask, probs);
    ctx_kernel<<<dim3(Sn/128, BHn), 256, smem3>>>(probs, ctx);
}